// round 7
// baseline (speedup 1.0000x reference)
#include <cuda_runtime.h>
#include <math.h>

#define B_ 8
#define T_ 4096
#define D_ 1024
#define NCHUNK 64
#define CH (T_ / NCHUNK)        // 64 rows per k_main chunk
#define NBLK (B_ * NCHUNK)      // 512 k_main blocks
#define NSUB 128                // sub-chunks (32 rows each) for pre/scan
#define CH2 (T_ / NSUB)         // 32 rows per k_pre block
#define NBLK2 (B_ * NSUB)       // 1024 k_pre blocks
#define THREADS 256             // 4 d-lanes per thread
#define G 8                     // rows per barrier group

// Scratch (allocation-free rule: device globals)
__device__ float2 g_cum[NBLK2 * D_];   // (sum_x, sum_sq) per (sub-chunk, d)
__device__ float4 g_row[B_ * T_];      // per-row (s1_sum, dot_raw, nm, 0)
__device__ float2 g_rowc[B_ * T_];     // per-row gate constants (c0, c1)
__device__ float  g_scal[8];           // tau, w, a1, a3, sig1, sig3, s2p, invN

__device__ __forceinline__ float tanh_fast(float x) {
    float y; asm("tanh.approx.f32 %0, %1;" : "=f"(y) : "f"(x)); return y;
}
__device__ __forceinline__ float ex2_fast(float x) {
    float y; asm("ex2.approx.f32 %0, %1;" : "=f"(y) : "f"(x)); return y;
}
__device__ __forceinline__ float lg2_fast(float x) {
    float y; asm("lg2.approx.f32 %0, %1;" : "=f"(y) : "f"(x)); return y;
}

// ---------------------------------------------------------------------------
// Kernel 1: pass 1 — chunk sums for the scan + scan-independent row signals
// (s1, gelu·ema_out, gelu²).  Block 0 also computes global scalars.
// ---------------------------------------------------------------------------
__global__ void __launch_bounds__(THREADS) k_pre(
        const float4* __restrict__ x,
        const float* __restrict__ ema_mean,
        const float* __restrict__ ema_sq,
        const float* __restrict__ ema_out,
        const float* __restrict__ var_fast,
        const float* __restrict__ var_slow,
        const float* __restrict__ lt,  const float* __restrict__ ls1,
        const float* __restrict__ ls2, const float* __restrict__ ls3,
        const float* __restrict__ lw,  const float* __restrict__ la1,
        const float* __restrict__ la2, const float* __restrict__ la3) {
    __shared__ float4 smA[2][G][32];   // [parity][row][warp*4 + sublane]
    int blk = blockIdx.x, tid = threadIdx.x;
    int lane = tid & 31, wid = tid >> 5;

    int d0 = tid * 4;
    float A[4], Bc[4], EO[4];
    #pragma unroll
    for (int j = 0; j < 4; j++) {
        float m = ema_mean[d0 + j];
        float v = fmaxf(ema_sq[d0 + j] - m * m, 1e-4f);
        float rs = 1.0f / (sqrtf(v) + 1e-5f);
        A[j]  = rs;
        Bc[j] = -m * rs;
        EO[j] = ema_out[d0 + j];            // raw; invN folded in k_rowgate
    }
    float sx[4] = {0.f, 0.f, 0.f, 0.f}, sq[4] = {0.f, 0.f, 0.f, 0.f};

    long base = (long)blk * CH2 * (D_ / 4) + tid;
    int row0 = blk * CH2;

    for (int g = 0; g < CH2 / G; g++) {
        int p = g & 1;
        #pragma unroll
        for (int r = 0; r < G; r++) {
            float4 xv = x[base + (long)(g * G + r) * (D_ / 4)];
            float xe[4] = { xv.x, xv.y, xv.z, xv.w };
            float s1 = 0.f, dt = 0.f, nm = 0.f;
            #pragma unroll
            for (int j = 0; j < 4; j++) {
                float xx = xe[j];
                float x2 = xx * xx;
                float q  = fmaf(0.0356774081363f, x2, 0.7978845608028654f);
                float th = tanh_fast(xx * q);
                float h  = 0.5f * xx;
                float gg = fmaf(h, th, h);
                s1 += fabsf(fmaf(xx, A[j], Bc[j]));
                dt = fmaf(gg, EO[j], dt);
                nm = fmaf(gg, gg, nm);
                sx[j] += xx;
                sq[j] = fmaf(xx, xx, sq[j]);
            }
            #pragma unroll
            for (int o = 16; o >= 4; o >>= 1) {
                s1 += __shfl_xor_sync(0xffffffffu, s1, o);
                dt += __shfl_xor_sync(0xffffffffu, dt, o);
                nm += __shfl_xor_sync(0xffffffffu, nm, o);
            }
            if (lane < 4)
                smA[p][r][wid * 4 + lane] = make_float4(s1, dt, nm, 0.f);
        }
        __syncthreads();
        // warp `wid` reduces row `wid`, writes raw row sums to global
        {
            float4 v = smA[p][wid][lane];
            #pragma unroll
            for (int o = 16; o; o >>= 1) {
                v.x += __shfl_xor_sync(0xffffffffu, v.x, o);
                v.y += __shfl_xor_sync(0xffffffffu, v.y, o);
                v.z += __shfl_xor_sync(0xffffffffu, v.z, o);
            }
            if (lane == 0) g_row[row0 + g * G + wid] = v;
        }
        // single barrier per group: next group writes smA[p^1] (double buffer)
    }

    int ci = blk * (D_ / 2) + tid * 2;     // float4 view of g_cum
    ((float4*)g_cum)[ci]     = make_float4(sx[0], sq[0], sx[1], sq[1]);
    ((float4*)g_cum)[ci + 1] = make_float4(sx[2], sq[2], sx[3], sq[3]);

    // ---- scalar precompute on block 0 only ----
    if (blk == 0) {
        __shared__ float shr[8], she[8];
        float r = 0.f, e = 0.f;
        #pragma unroll
        for (int i = 0; i < 4; i++) {
            int d = tid + i * 256;
            r += fminf(var_fast[d] / fmaxf(var_slow[d], 1e-4f), 10.0f);
            float ev = ema_out[d];
            e = fmaf(ev, ev, e);
        }
        #pragma unroll
        for (int o = 16; o; o >>= 1) {
            r += __shfl_xor_sync(0xffffffffu, r, o);
            e += __shfl_xor_sync(0xffffffffu, e, o);
        }
        if (lane == 0) { shr[wid] = r; she[wid] = e; }
        __syncthreads();
        if (tid == 0) {
            float rs = 0.f, es = 0.f;
            #pragma unroll
            for (int i = 0; i < 8; i++) { rs += shr[i]; es += she[i]; }
            float tau  = expf(lt[0]);
            float sig1 = log1pf(expf(ls1[0]));
            float sig2 = log1pf(expf(ls2[0]));
            float sig3 = log1pf(expf(ls3[0]));
            float w    = log1pf(expf(lw[0]));
            float a1   = log1pf(expf(la1[0]));
            float a2   = log1pf(expf(la2[0]));
            float a3   = log1pf(expf(la3[0]));
            float burst = fmaxf(rs / (float)D_ - 1.0f, 0.0f);
            float surp2 = tanhf(sig2 * burst);
            float s2p   = powf(fmaxf(surp2, 1e-7f), a2);
            g_scal[0] = tau;  g_scal[1] = w;    g_scal[2] = a1;  g_scal[3] = a3;
            g_scal[4] = sig1; g_scal[5] = sig3; g_scal[6] = s2p;
            g_scal[7] = 1.0f / fmaxf(sqrtf(es), 1e-12f);
        }
    }
}

// ---------------------------------------------------------------------------
// Kernel 2: in-place exclusive scan over sub-chunks, per (b, d)
// ---------------------------------------------------------------------------
__global__ void k_scan() {
    int idx = blockIdx.x * blockDim.x + threadIdx.x;   // 0 .. B_*D_-1
    int b = idx >> 10;
    int d = idx & (D_ - 1);
    float rx = 0.f, rq = 0.f;
    int base = b * NSUB * D_ + d;
    for (int c0 = 0; c0 < NSUB; c0 += 8) {
        float2 tv[8];
        #pragma unroll
        for (int k = 0; k < 8; k++) tv[k] = g_cum[base + (c0 + k) * D_];
        #pragma unroll
        for (int k = 0; k < 8; k++) {
            g_cum[base + (c0 + k) * D_] = make_float2(rx, rq);
            rx += tv[k].x; rq += tv[k].y;
        }
    }
}

// ---------------------------------------------------------------------------
// Kernel 3: per-row gate constants from scan-independent signals
//   gate(t) = c0 + c1 * p3(s3)   with  c0 = gcos, c1 = gcos*w*s2p*p1
// ---------------------------------------------------------------------------
__global__ void k_rowgate() {
    int idx = blockIdx.x * blockDim.x + threadIdx.x;   // 0 .. B_*T_-1
    float4 v = g_row[idx];
    float tau = g_scal[0], w = g_scal[1], a1 = g_scal[2];
    float sig1 = g_scal[4], s2p = g_scal[6], invN = g_scal[7];
    float surp1 = tanh_fast(sig1 * v.x * (1.0f / (float)D_));
    float p1 = ex2_fast(a1 * lg2_fast(fmaxf(surp1, 1e-7f)));
    float cs = v.y * invN * rsqrtf(fmaxf(v.z, 1e-24f));
    cs = fminf(fmaxf(cs, -1.0f), 1.0f);
    float gcos = ex2_fast(-1.4426950408889634f * tau * cs);
    g_rowc[idx] = make_float2(gcos, gcos * w * s2p * p1);
}

// ---------------------------------------------------------------------------
// Kernel 4: main fused pass — gelu + z3 only; single-variable reduction
// ---------------------------------------------------------------------------
__global__ void __launch_bounds__(THREADS, 3) k_main(const float4* __restrict__ x,
                                                     float4* __restrict__ out) {
    __shared__ float smA[2][G][32];      // [parity][row][warp*4 + sublane]
    __shared__ float gatesS[2][G];
    int blk = blockIdx.x, tid = threadIdx.x;
    int c = blk & (NCHUNK - 1);
    int lane = tid & 31, wid = tid >> 5;

    float sig3 = g_scal[5], a3 = g_scal[3];

    float cumx[4], cumsq[4];
    {   // exclusive prefix at row c*64 = scan value at sub-chunk 2c
        int sub = (blk >> 6) * NSUB + c * 2;
        int ci = sub * (D_ / 2) + tid * 2;
        float4 c01 = ((const float4*)g_cum)[ci];
        float4 c23 = ((const float4*)g_cum)[ci + 1];
        cumx[0] = c01.x; cumsq[0] = c01.y; cumx[1] = c01.z; cumsq[1] = c01.w;
        cumx[2] = c23.x; cumsq[2] = c23.y; cumx[3] = c23.z; cumsq[3] = c23.w;
    }

    long base = (long)blk * CH * (D_ / 4) + tid;
    int t0 = c * CH;
    int rowbase = blk * CH;              // global flattened row index base

    for (int g = 0; g < CH / G; g++) {
        int p = g & 1;
        float gv[G][4];
        // per-warp gate constants for the row this warp reduces in phase B
        float2 cc = g_rowc[rowbase + g * G + wid];

        // ---------- phase A: gelu + z3, 3-level partial reduce (s3 only) ----
        #pragma unroll
        for (int r = 0; r < G; r++) {
            int t = t0 + g * G + r;
            float tf  = (float)t;
            float c5  = 1e-5f * tf;
            float tt4 = (t > 0) ? 1e-4f * tf * tf : 1.0f;   // t=0 -> z3 term 0

            float4 xv = x[base + (long)(g * G + r) * (D_ / 4)];
            float xe[4] = { xv.x, xv.y, xv.z, xv.w };
            float s3 = 0.f;
            #pragma unroll
            for (int j = 0; j < 4; j++) {
                float xx = xe[j];
                float x2 = xx * xx;
                float q  = fmaf(0.0356774081363f, x2, 0.7978845608028654f);
                float th = tanh_fast(xx * q);
                float h  = 0.5f * xx;
                gv[r][j] = fmaf(h, th, h);
                float P = cumx[j], Q = cumsq[j];
                float dd = fmaf(xx, tf, -P);
                float wv = fmaxf(fmaf(-P, P, tf * Q), tt4);
                float rr = rsqrtf(wv);
                float f  = fmaf(-c5, rr, 1.0f) * rr;
                s3 = fmaf(fabsf(dd), f, s3);
                cumx[j]  = P + xx;
                cumsq[j] = Q + x2;
            }
            #pragma unroll
            for (int o = 16; o >= 4; o >>= 1)
                s3 += __shfl_xor_sync(0xffffffffu, s3, o);
            if (lane < 4)
                smA[p][r][wid * 4 + lane] = s3;
        }
        __syncthreads();

        // ---------- phase B: warp `wid` finishes row `wid`, gate ----------
        {
            float v = smA[p][wid][lane];
            #pragma unroll
            for (int o = 16; o; o >>= 1)
                v += __shfl_xor_sync(0xffffffffu, v, o);
            float surp3 = tanh_fast(sig3 * v * (1.0f / (float)D_));
            float p3 = ex2_fast(a3 * lg2_fast(fmaxf(surp3, 1e-7f)));
            if (lane == 0) gatesS[p][wid] = fmaf(cc.y, p3, cc.x);
        }
        __syncthreads();

        // ---------- phase C: scale + store ----------
        #pragma unroll
        for (int r = 0; r < G; r++) {
            float gate = gatesS[p][r];
            out[base + (long)(g * G + r) * (D_ / 4)] =
                make_float4(gv[r][0] * gate, gv[r][1] * gate,
                            gv[r][2] * gate, gv[r][3] * gate);
        }
    }
}

// ---------------------------------------------------------------------------
extern "C" void kernel_launch(void* const* d_in, const int* in_sizes, int n_in,
                              void* d_out, int out_size) {
    const float* x        = (const float*)d_in[0];
    const float* ema_mean = (const float*)d_in[1];
    const float* ema_sq   = (const float*)d_in[2];
    const float* ema_out  = (const float*)d_in[3];
    const float* var_fast = (const float*)d_in[4];
    const float* var_slow = (const float*)d_in[5];

    k_pre<<<NBLK2, THREADS>>>((const float4*)x, ema_mean, ema_sq, ema_out,
                              var_fast, var_slow,
                              (const float*)d_in[6],  (const float*)d_in[7],
                              (const float*)d_in[8],  (const float*)d_in[9],
                              (const float*)d_in[10], (const float*)d_in[11],
                              (const float*)d_in[12], (const float*)d_in[13]);
    k_scan<<<(B_ * D_) / 256, 256>>>();
    k_rowgate<<<(B_ * T_) / 256, 256>>>();
    k_main<<<NBLK, THREADS>>>((const float4*)x, (float4*)d_out);
}

// round 8
// speedup vs baseline: 1.7999x; 1.7999x over previous
#include <cuda_runtime.h>
#include <math.h>

#define B_ 8
#define T_ 4096
#define D_ 1024
#define NCHUNK 128
#define CH (T_ / NCHUNK)        // 32 rows per k_main block
#define NBLK (B_ * NCHUNK)      // 1024 k_main blocks
#define NSUB 128                // scan sub-chunks (32 rows each)
#define CH2 (T_ / NSUB)         // 32 rows per k_partial block
#define NBLK2 (B_ * NSUB)       // 1024 k_partial blocks
#define THREADS 256             // 4 d-lanes per thread
#define G 8                     // rows per barrier group

// Scratch (allocation-free rule: device globals)
__device__ float2 g_cum[NBLK2 * D_];   // (sum_x, sum_sq) per (sub-chunk, d)
__device__ float  g_scal[8];           // tau, w, a1, a3, sig1, sig3, s2p, invN

__device__ __forceinline__ float tanh_fast(float x) {
    float y; asm("tanh.approx.f32 %0, %1;" : "=f"(y) : "f"(x)); return y;
}
__device__ __forceinline__ float ex2_fast(float x) {
    float y; asm("ex2.approx.f32 %0, %1;" : "=f"(y) : "f"(x)); return y;
}
__device__ __forceinline__ float lg2_fast(float x) {
    float y; asm("lg2.approx.f32 %0, %1;" : "=f"(y) : "f"(x)); return y;
}

// ---------------------------------------------------------------------------
// Kernel 1: per-sub-chunk sums of x and x^2 (register-lean, high occupancy);
// block 0 also computes global scalars.
// ---------------------------------------------------------------------------
__global__ void __launch_bounds__(THREADS) k_partial(
        const float4* __restrict__ x,
        const float* __restrict__ ema_out,
        const float* __restrict__ var_fast,
        const float* __restrict__ var_slow,
        const float* __restrict__ lt,  const float* __restrict__ ls1,
        const float* __restrict__ ls2, const float* __restrict__ ls3,
        const float* __restrict__ lw,  const float* __restrict__ la1,
        const float* __restrict__ la2, const float* __restrict__ la3) {
    int blk = blockIdx.x;                // sub-chunks contiguous in memory
    int tid = threadIdx.x;
    long base = (long)blk * CH2 * (D_ / 4) + tid;
    float sx0 = 0.f, sx1 = 0.f, sx2 = 0.f, sx3 = 0.f;
    float sq0 = 0.f, sq1 = 0.f, sq2 = 0.f, sq3 = 0.f;
    #pragma unroll 8
    for (int r = 0; r < CH2; r++) {
        float4 v = x[base + (long)r * (D_ / 4)];
        sx0 += v.x; sx1 += v.y; sx2 += v.z; sx3 += v.w;
        sq0 = fmaf(v.x, v.x, sq0); sq1 = fmaf(v.y, v.y, sq1);
        sq2 = fmaf(v.z, v.z, sq2); sq3 = fmaf(v.w, v.w, sq3);
    }
    int ci = blk * (D_ / 2) + tid * 2;   // float4 view of g_cum
    ((float4*)g_cum)[ci]     = make_float4(sx0, sq0, sx1, sq1);
    ((float4*)g_cum)[ci + 1] = make_float4(sx2, sq2, sx3, sq3);

    if (blk == 0) {
        __shared__ float shr[8], she[8];
        float r = 0.f, e = 0.f;
        #pragma unroll
        for (int i = 0; i < 4; i++) {
            int d = tid + i * 256;
            r += fminf(var_fast[d] / fmaxf(var_slow[d], 1e-4f), 10.0f);
            float ev = ema_out[d];
            e = fmaf(ev, ev, e);
        }
        #pragma unroll
        for (int o = 16; o; o >>= 1) {
            r += __shfl_xor_sync(0xffffffffu, r, o);
            e += __shfl_xor_sync(0xffffffffu, e, o);
        }
        if ((tid & 31) == 0) { shr[tid >> 5] = r; she[tid >> 5] = e; }
        __syncthreads();
        if (tid == 0) {
            float rs = 0.f, es = 0.f;
            #pragma unroll
            for (int i = 0; i < 8; i++) { rs += shr[i]; es += she[i]; }
            float tau  = expf(lt[0]);
            float sig1 = log1pf(expf(ls1[0]));
            float sig2 = log1pf(expf(ls2[0]));
            float sig3 = log1pf(expf(ls3[0]));
            float w    = log1pf(expf(lw[0]));
            float a1   = log1pf(expf(la1[0]));
            float a2   = log1pf(expf(la2[0]));
            float a3   = log1pf(expf(la3[0]));
            float burst = fmaxf(rs / (float)D_ - 1.0f, 0.0f);
            float surp2 = tanhf(sig2 * burst);
            float s2p   = powf(fmaxf(surp2, 1e-7f), a2);
            g_scal[0] = tau;  g_scal[1] = w;    g_scal[2] = a1;  g_scal[3] = a3;
            g_scal[4] = sig1; g_scal[5] = sig3; g_scal[6] = s2p;
            g_scal[7] = 1.0f / fmaxf(sqrtf(es), 1e-12f);
        }
    }
}

// ---------------------------------------------------------------------------
// Kernel 2: in-place exclusive scan over sub-chunks, per (b, d)
// ---------------------------------------------------------------------------
__global__ void k_scan() {
    int idx = blockIdx.x * blockDim.x + threadIdx.x;   // 0 .. B_*D_-1
    int b = idx >> 10;
    int d = idx & (D_ - 1);
    float rx = 0.f, rq = 0.f;
    int base = b * NSUB * D_ + d;
    for (int c0 = 0; c0 < NSUB; c0 += 8) {
        float2 tv[8];
        #pragma unroll
        for (int k = 0; k < 8; k++) tv[k] = g_cum[base + (c0 + k) * D_];
        #pragma unroll
        for (int k = 0; k < 8; k++) {
            g_cum[base + (c0 + k) * D_] = make_float2(rx, rq);
            rx += tv[k].x; rq += tv[k].y;
        }
    }
}

// ---------------------------------------------------------------------------
// Kernel 3: main fused pass.  Gelu values staged through smem (low regs);
// phase B+C fused: warp w reduces, gates, and stores row w itself.
// ---------------------------------------------------------------------------
__global__ void __launch_bounds__(THREADS, 4) k_main(const float4* __restrict__ x,
                                                     const float* __restrict__ ema_mean,
                                                     const float* __restrict__ ema_sq,
                                                     const float* __restrict__ ema_out,
                                                     float4* __restrict__ out) {
    __shared__ float4 sG[G][THREADS];    // gelu values, 32 KB
    __shared__ float4 smA[G][32];        // per-row 32 partials of (s1,s3,dt,nm)
    int blk = blockIdx.x, tid = threadIdx.x;
    int c = blk & (NCHUNK - 1);
    int lane = tid & 31, wid = tid >> 5;

    float tau  = g_scal[0], w    = g_scal[1], a1  = g_scal[2], a3   = g_scal[3];
    float sig1 = g_scal[4], sig3 = g_scal[5], s2p = g_scal[6], invN = g_scal[7];
    float ws2p = w * s2p;

    int d0 = tid * 4;
    float A[4], Bc[4], EN[4], cumx[4], cumsq[4];
    #pragma unroll
    for (int j = 0; j < 4; j++) {
        float m = ema_mean[d0 + j];
        float v = fmaxf(ema_sq[d0 + j] - m * m, 1e-4f);
        float rs = 1.0f / (sqrtf(v) + 1e-5f);
        A[j]  = rs;
        Bc[j] = -m * rs;
        EN[j] = ema_out[d0 + j] * invN;
    }
    {   // exclusive prefix at this block's first row (sub-chunk == chunk here)
        int ci = blk * (D_ / 2) + tid * 2;
        float4 c01 = ((const float4*)g_cum)[ci];
        float4 c23 = ((const float4*)g_cum)[ci + 1];
        cumx[0] = c01.x; cumsq[0] = c01.y; cumx[1] = c01.z; cumsq[1] = c01.w;
        cumx[2] = c23.x; cumsq[2] = c23.y; cumx[3] = c23.z; cumsq[3] = c23.w;
    }

    long base = (long)blk * CH * (D_ / 4);
    int t0 = c * CH;

    for (int g = 0; g < CH / G; g++) {
        // ---------- phase A: element math, gelu -> smem, 3-level reduce ----
        #pragma unroll
        for (int r = 0; r < G; r++) {
            int t = t0 + g * G + r;
            float tf  = (float)t;
            float c5  = 1e-5f * tf;
            float tt4 = (t > 0) ? 1e-4f * tf * tf : 1.0f;   // t=0 -> z3 term 0

            float4 xv = x[base + (long)(g * G + r) * (D_ / 4) + tid];
            float xe[4] = { xv.x, xv.y, xv.z, xv.w };
            float gv[4];
            float s1 = 0.f, s3 = 0.f, dt = 0.f, nm = 0.f;
            #pragma unroll
            for (int j = 0; j < 4; j++) {
                float xx = xe[j];
                float x2 = xx * xx;
                float q  = fmaf(0.0356774081363f, x2, 0.7978845608028654f);
                float th = tanh_fast(xx * q);
                float h  = 0.5f * xx;
                float gg = fmaf(h, th, h);
                gv[j] = gg;
                s1 += fabsf(fmaf(xx, A[j], Bc[j]));
                float P = cumx[j], Q = cumsq[j];
                float dd = fmaf(xx, tf, -P);
                float wv = fmaxf(fmaf(-P, P, tf * Q), tt4);
                float rr = rsqrtf(wv);
                float f  = fmaf(-c5, rr, 1.0f) * rr;
                s3 = fmaf(fabsf(dd), f, s3);
                dt = fmaf(gg, EN[j], dt);
                nm = fmaf(gg, gg, nm);
                cumx[j]  = P + xx;
                cumsq[j] = Q + x2;
            }
            sG[r][tid] = make_float4(gv[0], gv[1], gv[2], gv[3]);
            #pragma unroll
            for (int o = 16; o >= 4; o >>= 1) {
                s1 += __shfl_xor_sync(0xffffffffu, s1, o);
                s3 += __shfl_xor_sync(0xffffffffu, s3, o);
                dt += __shfl_xor_sync(0xffffffffu, dt, o);
                nm += __shfl_xor_sync(0xffffffffu, nm, o);
            }
            if (lane < 4)
                smA[r][wid * 4 + lane] = make_float4(s1, s3, dt, nm);
        }
        __syncthreads();

        // ---------- phase B+C: warp `wid` owns row `wid` completely --------
        {
            float4 v = smA[wid][lane];
            #pragma unroll
            for (int o = 16; o; o >>= 1) {
                v.x += __shfl_xor_sync(0xffffffffu, v.x, o);
                v.y += __shfl_xor_sync(0xffffffffu, v.y, o);
                v.z += __shfl_xor_sync(0xffffffffu, v.z, o);
                v.w += __shfl_xor_sync(0xffffffffu, v.w, o);
            }
            // every lane has totals -> compute gate redundantly (no broadcast)
            float surp1 = tanh_fast(sig1 * v.x * (1.0f / (float)D_));
            float surp3 = tanh_fast(sig3 * v.y * (1.0f / (float)D_));
            float cs = v.z * rsqrtf(fmaxf(v.w, 1e-24f));
            cs = fminf(fmaxf(cs, -1.0f), 1.0f);
            float gcos = ex2_fast(-1.4426950408889634f * tau * cs);
            float p1 = ex2_fast(a1 * lg2_fast(fmaxf(surp1, 1e-7f)));
            float p3 = ex2_fast(a3 * lg2_fast(fmaxf(surp3, 1e-7f)));
            float gate = gcos * fmaf(ws2p, p1 * p3, 1.0f);

            long rowo = base + (long)(g * G + wid) * (D_ / 4);
            #pragma unroll
            for (int k = 0; k < 8; k++) {
                int idx = lane + k * 32;
                float4 gg = sG[wid][idx];
                out[rowo + idx] = make_float4(gg.x * gate, gg.y * gate,
                                              gg.z * gate, gg.w * gate);
            }
        }
        __syncthreads();   // protect sG/smA before next group's phase A
    }
}

// ---------------------------------------------------------------------------
extern "C" void kernel_launch(void* const* d_in, const int* in_sizes, int n_in,
                              void* d_out, int out_size) {
    const float* x        = (const float*)d_in[0];
    const float* ema_mean = (const float*)d_in[1];
    const float* ema_sq   = (const float*)d_in[2];
    const float* ema_out  = (const float*)d_in[3];
    const float* var_fast = (const float*)d_in[4];
    const float* var_slow = (const float*)d_in[5];

    k_partial<<<NBLK2, THREADS>>>((const float4*)x, ema_out, var_fast, var_slow,
                                  (const float*)d_in[6],  (const float*)d_in[7],
                                  (const float*)d_in[8],  (const float*)d_in[9],
                                  (const float*)d_in[10], (const float*)d_in[11],
                                  (const float*)d_in[12], (const float*)d_in[13]);
    k_scan<<<(B_ * D_) / 256, 256>>>();
    k_main<<<NBLK, THREADS>>>((const float4*)x, ema_mean, ema_sq, ema_out, (float4*)d_out);
}